// round 7
// baseline (speedup 1.0000x reference)
#include <cuda_runtime.h>

#define INC   32
#define INN   50000
#define OUTC  32
#define OUTN  8192
#define MAXD  16
#define NB    8
#define NC    256   // N * OUTC (= N * INC)
#define TILE_O 16

// 51.2 MB scratch: z[i][n*32 + outc] = sum_c x[n][c][i] * W[c][outc]
__device__ float g_z[(size_t)INN * NC];

// ---------------------------------------------------------------------------
// Kernel 1: fused transpose + weight. Block = 32 i-values x one n.
//   Loads the 32c x 32i tile of x (1 LDG.128/thread), computes the 32x32x32
//   matmul z_tile[i][outc] = sum_c tile[c][i] * W[c][outc], writes z.
// ---------------------------------------------------------------------------
__global__ __launch_bounds__(256) void embed_kernel(
    const float* __restrict__ x,
    const float* __restrict__ w)
{
    __shared__ float tile[32][32];   // [c][i]
    __shared__ float w_s[32 * 32];   // [c][outc]

    const int i0  = blockIdx.x * 32;
    const int n   = blockIdx.y;
    const int tid = threadIdx.y * 32 + threadIdx.x;

    // Stage weight (1024 floats)
    #pragma unroll
    for (int k = 0; k < 4; ++k)
        w_s[tid + k * 256] = w[tid + k * 256];

    // Load tile: thread -> (c = tid>>3, iq = tid&7), one float4 along i
    {
        const int c  = tid >> 3;
        const int iq = tid & 7;
        const int i  = i0 + iq * 4;
        float4 v = make_float4(0.f, 0.f, 0.f, 0.f);
        if (i < INN)   // INN % 4 == 0, so a full in-range float4
            v = *(const float4*)&x[(size_t)(n * 32 + c) * INN + i];
        *(float4*)&tile[c][iq * 4] = v;
    }
    __syncthreads();

    // Compute: thread (tx = i, ty) owns outc quad [ty*4, ty*4+4)
    const int tx = threadIdx.x;
    const int ty = threadIdx.y;
    float4 acc = make_float4(0.f, 0.f, 0.f, 0.f);
    #pragma unroll
    for (int c = 0; c < 32; ++c) {
        const float  v  = tile[c][tx];                            // conflict-free
        const float4 wv = *(const float4*)&w_s[c * 32 + ty * 4];  // broadcast
        acc.x += v * wv.x; acc.y += v * wv.y;
        acc.z += v * wv.z; acc.w += v * wv.w;
    }
    if (i0 + tx < INN)
        *(float4*)&g_z[(size_t)(i0 + tx) * NC + n * 32 + ty * 4] = acc;
}

// ---------------------------------------------------------------------------
// Kernel 2: pure gather + masked pool + bias. TILE_O=16, grid=512.
//   Phase A: thread (o_sub = tid>>6, col = tid&63) accumulates one float4
//     over 16 neighbors per o-group (LDG.128 from 1 KB z rows).
//   Store:   thread r = tid writes its 16 o-values (+bias) as 4 float4.
// ---------------------------------------------------------------------------
__global__ __launch_bounds__(256, 6) void pool_kernel(
    const int*   __restrict__ A,
    const float* __restrict__ mask,
    const float* __restrict__ bias,
    float*       __restrict__ out)
{
    __shared__ float pooled_s[TILE_O][260];   // [o][r]
    __shared__ int   a_s[TILE_O * MAXD];
    __shared__ float m_s[TILE_O * MAXD];

    const int tid    = threadIdx.x;
    const int o_base = blockIdx.x * TILE_O;

    a_s[tid] = A[o_base * MAXD + tid];        // 256 = TILE_O*MAXD
    m_s[tid] = mask[o_base * MAXD + tid];
    __syncthreads();

    // ---- Phase A: vectorized gather + masked pool ----
    const float4* __restrict__ z4 = (const float4*)g_z;
    const int o_sub = tid >> 6;      // 0..3
    const int col   = tid & 63;      // float4 column within the 256-row

    #pragma unroll
    for (int g = 0; g < TILE_O / 4; ++g) {
        const int o = g * 4 + o_sub;
        float4 acc = make_float4(0.f, 0.f, 0.f, 0.f);
        #pragma unroll
        for (int d = 0; d < MAXD; ++d) {
            const int   idx = a_s[o * MAXD + d];                 // broadcast
            const float m   = m_s[o * MAXD + d];                 // broadcast
            const float4 v  = z4[(size_t)idx * (NC / 4) + col];  // LDG.128
            acc.x += m * v.x; acc.y += m * v.y;
            acc.z += m * v.z; acc.w += m * v.w;
        }
        *(float4*)&pooled_s[o][col * 4] = acc;                   // conflict-free
    }
    __syncthreads();

    // ---- Store: thread r = tid = n*32+outc, 16 o-values + bias ----
    const int outc = tid & 31;
    const float* __restrict__ brow = &bias[(size_t)outc * OUTN + o_base];
    float*       __restrict__ orow = &out[(size_t)tid * OUTN + o_base];

    #pragma unroll
    for (int j = 0; j < 4; ++j) {
        const float4 b = *(const float4*)&brow[j * 4];
        float4 v;
        v.x = pooled_s[j * 4 + 0][tid] + b.x;
        v.y = pooled_s[j * 4 + 1][tid] + b.y;
        v.z = pooled_s[j * 4 + 2][tid] + b.z;
        v.w = pooled_s[j * 4 + 3][tid] + b.w;
        *(float4*)&orow[j * 4] = v;
    }
}

// ---------------------------------------------------------------------------
// Launch
// ---------------------------------------------------------------------------
extern "C" void kernel_launch(void* const* d_in, const int* in_sizes, int n_in,
                              void* d_out, int out_size)
{
    const float* x      = (const float*)d_in[0];  // [8, 32, 50000] f32
    const int*   A      = (const int*)  d_in[1];  // [8192, 16] i32
    const float* mask   = (const float*)d_in[2];  // [8192, 16, 1] f32
    const float* weight = (const float*)d_in[3];  // [32, 32] f32
    const float* bias   = (const float*)d_in[4];  // [32, 8192] f32
    float*       out    = (float*)d_out;          // [8, 32, 8192] f32

    dim3 tb(32, 8);
    dim3 tg((INN + 31) / 32, NB);
    embed_kernel<<<tg, tb>>>(x, weight);

    pool_kernel<<<OUTN / TILE_O, 256>>>(A, mask, bias, out);
}

// round 8
// speedup vs baseline: 2.9065x; 2.9065x over previous
#include <cuda_runtime.h>

#define INC   32
#define INN   50000
#define OUTC  32
#define OUTN  8192
#define MAXD  16
#define NB    8
#define NC    256   // N * INC
#define TILE_O 8
#define PSTRIDE 292  // row stride for pooled_s; 292 % 32 == 4 -> conflict-free

// 51.2 MB scratch for the transposed embedding table xT[i][n*32+c] = x[n][c][i]
__device__ float g_xT[(size_t)INN * NC];

// ---------------------------------------------------------------------------
// Kernel 1: tiled transpose x [256 rows x 50000 cols] -> g_xT [50000 x 256]
// (R3-proven: coalesced 128B loads AND stores via 32x33 smem tile)
// ---------------------------------------------------------------------------
__global__ __launch_bounds__(256) void transpose_kernel(const float* __restrict__ x) {
    __shared__ float tile[32][33];
    const int i0 = blockIdx.x * 32;      // column tile (along INN)
    const int r0 = blockIdx.y * 32;      // row tile (along 256 = n*32+c)
    const int tx = threadIdx.x;
    const int ty = threadIdx.y;

    #pragma unroll
    for (int k = 0; k < 32; k += 8) {
        const int i = i0 + tx;
        const int r = r0 + ty + k;       // r < 256 always (gridDim.y = 8)
        tile[ty + k][tx] = (i < INN) ? x[(size_t)r * INN + i] : 0.0f;
    }
    __syncthreads();
    #pragma unroll
    for (int k = 0; k < 32; k += 8) {
        const int i = i0 + ty + k;
        if (i < INN)
            g_xT[(size_t)i * NC + (r0 + tx)] = tile[tx][ty + k];  // lanes along r: 128B
    }
}

// ---------------------------------------------------------------------------
// Kernel 2: TILE_O=8 outputs per block, grid=1024 (~6 CTAs/SM).
//   Phase A: thread (o_sub=tid>>6, col=tid&63) pools one float4 per o-group
//     from 1KB xT rows (LDG.128). Smem layout [o][n*33+c], stride 292:
//     store bank = 4*o + n + c  -> conflict-free.
//   Phase B: thread (q=tid>>6, n=(tid>>3)&7, o=tid&7) computes 8 outc;
//     pooled read bank = 4*o + n + c over the warp -> conflict-free;
//     w_s reads are warp-broadcast.
// ---------------------------------------------------------------------------
__global__ __launch_bounds__(256, 6) void pool_mm_kernel(
    const int*   __restrict__ A,
    const float* __restrict__ mask,
    const float* __restrict__ weight,
    const float* __restrict__ bias,
    float*       __restrict__ out)
{
    __shared__ float pooled_s[TILE_O * PSTRIDE];
    __shared__ float w_s[INC * OUTC];
    __shared__ int   a_s[TILE_O * MAXD];   // 128
    __shared__ float m_s[TILE_O * MAXD];   // 128

    const int tid    = threadIdx.x;
    const int o_base = blockIdx.x * TILE_O;

    if (tid < TILE_O * MAXD) {
        a_s[tid] = A[o_base * MAXD + tid];
        m_s[tid] = mask[o_base * MAXD + tid];
    }
    #pragma unroll
    for (int k = 0; k < 4; ++k)
        w_s[tid + k * 256] = weight[tid + k * 256];
    __syncthreads();

    // ---- Phase A: vectorized gather + masked pool ----
    const float4* __restrict__ xT4 = (const float4*)g_xT;
    const int o_sub = tid >> 6;            // 0..3
    const int col   = tid & 63;            // float4 column: n = col>>3, c4 = (col&7)*4
    const int nA    = col >> 3;
    const int c4    = (col & 7) * 4;

    #pragma unroll
    for (int g = 0; g < TILE_O / 4; ++g) {
        const int o = g * 4 + o_sub;
        float4 acc = make_float4(0.f, 0.f, 0.f, 0.f);
        #pragma unroll
        for (int d = 0; d < MAXD; ++d) {
            const int   idx = a_s[o * MAXD + d];                 // broadcast
            const float m   = m_s[o * MAXD + d];                 // broadcast
            const float4 v  = xT4[(size_t)idx * (NC / 4) + col]; // LDG.128
            acc.x += m * v.x; acc.y += m * v.y;
            acc.z += m * v.z; acc.w += m * v.w;
        }
        float* p = &pooled_s[o * PSTRIDE + nA * 33 + c4];
        p[0] = acc.x; p[1] = acc.y; p[2] = acc.z; p[3] = acc.w;   // conflict-free
    }
    __syncthreads();

    // ---- Phase B: shared-weight matmul + bias ----
    const int o = tid & 7;                 // 0..7
    const int n = (tid >> 3) & 7;          // 0..7
    const int q = tid >> 6;                // 0..3 -> owns outc [q*8, q*8+8)

    float acc[8];
    #pragma unroll
    for (int k = 0; k < 8; ++k)
        acc[k] = bias[(size_t)(q * 8 + k) * OUTN + o_base + o];

    const float* prow = &pooled_s[o * PSTRIDE + n * 33];
    #pragma unroll
    for (int c = 0; c < INC; ++c) {
        const float p = prow[c];                         // conflict-free
        #pragma unroll
        for (int k = 0; k < 8; ++k)
            acc[k] += p * w_s[c * 32 + q * 8 + k];       // broadcast
    }

    #pragma unroll
    for (int k = 0; k < 8; ++k)
        out[(size_t)(n * OUTC + q * 8 + k) * OUTN + o_base + o] = acc[k];
}

// ---------------------------------------------------------------------------
// Launch
// ---------------------------------------------------------------------------
extern "C" void kernel_launch(void* const* d_in, const int* in_sizes, int n_in,
                              void* d_out, int out_size)
{
    const float* x      = (const float*)d_in[0];  // [8, 32, 50000] f32
    const int*   A      = (const int*)  d_in[1];  // [8192, 16] i32
    const float* mask   = (const float*)d_in[2];  // [8192, 16, 1] f32
    const float* weight = (const float*)d_in[3];  // [32, 32] f32
    const float* bias   = (const float*)d_in[4];  // [32, 8192] f32
    float*       out    = (float*)d_out;          // [8, 32, 8192] f32

    dim3 tb(32, 8);
    dim3 tg((INN + 31) / 32, NC / 32);
    transpose_kernel<<<tg, tb>>>(x);

    pool_mm_kernel<<<OUTN / TILE_O, 256>>>(A, mask, weight, bias, out);
}

// round 10
// speedup vs baseline: 2.9089x; 1.0008x over previous
#include <cuda_runtime.h>

#define INC   32
#define INN   50000
#define OUTC  32
#define OUTN  8192
#define MAXD  16
#define NB    8
#define NC    256   // N * INC
#define TILE_O 16

// 51.2 MB scratch for the transposed embedding table xT[i][n*32+c] = x[n][c][i]
__device__ float g_xT[(size_t)INN * NC];

// ---------------------------------------------------------------------------
// Kernel 1: tiled transpose x [256 rows x 50000 cols] -> g_xT [50000 x 256]
// (measured ~17.5us, ~5.9 TB/s effective -> near ceiling, keep as-is)
// ---------------------------------------------------------------------------
__global__ __launch_bounds__(256) void transpose_kernel(const float* __restrict__ x) {
    __shared__ float tile[32][33];
    const int i0 = blockIdx.x * 32;      // column tile (along INN)
    const int r0 = blockIdx.y * 32;      // row tile (along 256 = n*32+c)
    const int tx = threadIdx.x;
    const int ty = threadIdx.y;

    #pragma unroll
    for (int k = 0; k < 32; k += 8) {
        const int i = i0 + tx;
        const int r = r0 + ty + k;       // r < 256 always (gridDim.y = 8)
        tile[ty + k][tx] = (i < INN) ? x[(size_t)r * INN + i] : 0.0f;
    }
    __syncthreads();
    #pragma unroll
    for (int k = 0; k < 32; k += 8) {
        const int i = i0 + ty + k;
        if (i < INN)
            g_xT[(size_t)i * NC + (r0 + tx)] = tile[tx][ty + k];  // lanes along r: 128B
    }
}

// ---------------------------------------------------------------------------
// Kernel 2: TILE_O=16, grid=512 (R3-best config), phase A restructured for
//   max per-thread MLP: d-outer loop, 4 independent group-loads per step.
// ---------------------------------------------------------------------------
__global__ __launch_bounds__(256, 4) void pool_mm_kernel(
    const int*   __restrict__ A,
    const float* __restrict__ mask,
    const float* __restrict__ weight,
    const float* __restrict__ bias,
    float*       __restrict__ out)
{
    __shared__ float pooled_s[TILE_O][260];   // [o][r]
    __shared__ float w_s[INC * OUTC];
    __shared__ int   a_s[TILE_O * MAXD];      // 256
    __shared__ float m_s[TILE_O * MAXD];      // 256

    const int tid    = threadIdx.x;
    const int o_base = blockIdx.x * TILE_O;

    a_s[tid] = A[o_base * MAXD + tid];
    m_s[tid] = mask[o_base * MAXD + tid];
    #pragma unroll
    for (int k = 0; k < 4; ++k)
        w_s[tid + k * 256] = weight[tid + k * 256];
    __syncthreads();

    // ---- Phase A: gather + masked pool, 4 o-groups in flight ----
    const float4* __restrict__ z4 = (const float4*)g_xT;
    const int o_sub = tid >> 6;      // 0..3: this thread's o within each group
    const int col   = tid & 63;      // float4 column of the 256-row

    float4 acc0 = make_float4(0.f,0.f,0.f,0.f);
    float4 acc1 = make_float4(0.f,0.f,0.f,0.f);
    float4 acc2 = make_float4(0.f,0.f,0.f,0.f);
    float4 acc3 = make_float4(0.f,0.f,0.f,0.f);

    const int o0 = 0  + o_sub, o1 = 4  + o_sub, o2 = 8 + o_sub, o3 = 12 + o_sub;

    #pragma unroll
    for (int d = 0; d < MAXD; ++d) {
        // 4 independent gathers issued back-to-back (batched MLP)
        const float4 v0 = z4[(size_t)a_s[o0 * MAXD + d] * (NC / 4) + col];
        const float4 v1 = z4[(size_t)a_s[o1 * MAXD + d] * (NC / 4) + col];
        const float4 v2 = z4[(size_t)a_s[o2 * MAXD + d] * (NC / 4) + col];
        const float4 v3 = z4[(size_t)a_s[o3 * MAXD + d] * (NC / 4) + col];
        const float m0 = m_s[o0 * MAXD + d];
        const float m1 = m_s[o1 * MAXD + d];
        const float m2 = m_s[o2 * MAXD + d];
        const float m3 = m_s[o3 * MAXD + d];
        acc0.x += m0 * v0.x; acc0.y += m0 * v0.y; acc0.z += m0 * v0.z; acc0.w += m0 * v0.w;
        acc1.x += m1 * v1.x; acc1.y += m1 * v1.y; acc1.z += m1 * v1.z; acc1.w += m1 * v1.w;
        acc2.x += m2 * v2.x; acc2.y += m2 * v2.y; acc2.z += m2 * v2.z; acc2.w += m2 * v2.w;
        acc3.x += m3 * v3.x; acc3.y += m3 * v3.y; acc3.z += m3 * v3.z; acc3.w += m3 * v3.w;
    }
    *(float4*)&pooled_s[o0][col * 4] = acc0;   // conflict-free (bank=(col*4+o)%32)
    *(float4*)&pooled_s[o1][col * 4] = acc1;
    *(float4*)&pooled_s[o2][col * 4] = acc2;
    *(float4*)&pooled_s[o3][col * 4] = acc3;
    __syncthreads();

    // ---- Phase B: shared-weight matmul + bias (R3-proven) ----
    const int o    = tid & (TILE_O - 1);   // 0..15
    const int n    = (tid >> 4) & 7;       // 0..7
    const int half = tid >> 7;             // 0..1 -> owns 16 outc

    float acc[16];
    #pragma unroll
    for (int k = 0; k < 16; ++k)
        acc[k] = bias[(size_t)(half * 16 + k) * OUTN + o_base + o];

    #pragma unroll
    for (int c = 0; c < INC; ++c) {
        const float p = pooled_s[o][n * 32 + c];
        #pragma unroll
        for (int k = 0; k < 16; ++k)
            acc[k] += p * w_s[c * 32 + half * 16 + k];   // broadcast
    }

    #pragma unroll
    for (int k = 0; k < 16; ++k)
        out[(size_t)(n * OUTC + half * 16 + k) * OUTN + o_base + o] = acc[k];
}

// ---------------------------------------------------------------------------
// Launch
// ---------------------------------------------------------------------------
extern "C" void kernel_launch(void* const* d_in, const int* in_sizes, int n_in,
                              void* d_out, int out_size)
{
    const float* x      = (const float*)d_in[0];  // [8, 32, 50000] f32
    const int*   A      = (const int*)  d_in[1];  // [8192, 16] i32
    const float* mask   = (const float*)d_in[2];  // [8192, 16, 1] f32
    const float* weight = (const float*)d_in[3];  // [32, 32] f32
    const float* bias   = (const float*)d_in[4];  // [32, 8192] f32
    float*       out    = (float*)d_out;          // [8, 32, 8192] f32

    dim3 tb(32, 8);
    dim3 tg((INN + 31) / 32, NC / 32);
    transpose_kernel<<<tg, tb>>>(x);

    pool_mm_kernel<<<OUTN / TILE_O, 256>>>(A, mask, weight, bias, out);
}